// round 2
// baseline (speedup 1.0000x reference)
#include <cuda_runtime.h>
#include <cuda_bf16.h>
#include <cstdint>

#define NN 1000
#define FF 64
#define SS 192            // B*T snapshots
#define EMAX 16384
#define KD 576            // 9 slots * 64
#define ROWS (SS*NN)      // 192000
#define NSTAGE 18         // 576/32

// ---------------- scratch (static device memory; no runtime allocs) ----------------
__device__ float g_T[(size_t)ROWS * KD];       // A matrix, row-major [192000][576]
__device__ float g_gout[(size_t)ROWS * 128];   // GEMM output (z|h logits)
__device__ float g_hn[(size_t)ROWS * FF];      // normalized hidden
__device__ float g_W[KD * 128];                // combined weights [576][128]
__device__ float g_bias[128];
__device__ int   g_deg_out[NN], g_deg_in[NN];
__device__ float g_invdo[NN], g_invdi[NN];
__device__ int   g_ptr_o[NN + 1], g_ptr_i[NN + 1];
__device__ int   g_cur_o[NN], g_cur_i[NN];
__device__ int   g_src_o[EMAX];
__device__ float g_w_o[EMAX];
__device__ int   g_col_i[EMAX];
__device__ float g_part[192 * 40];

// ---------------- setup kernels ----------------
__global__ void k_zero() {
    for (int i = threadIdx.x; i < NN; i += blockDim.x) { g_deg_out[i] = 0; g_deg_in[i] = 0; }
}

__global__ void k_deg(const int* __restrict__ ei, int E) {
    int e = blockIdx.x * blockDim.x + threadIdx.x;
    if (e < E) {
        atomicAdd(&g_deg_out[ei[e]], 1);
        atomicAdd(&g_deg_in[ei[E + e]], 1);
    }
}

__global__ void k_scan() {
    __shared__ int sa[1024], sb[1024];
    int t = threadIdx.x;
    // --- indptr_o: buckets by col => sizes = deg_in ---
    int v = (t < NN) ? g_deg_in[t] : 0;
    sa[t] = v; __syncthreads();
    int* pin = sa; int* pout = sb;
    for (int off = 1; off < 1024; off <<= 1) {
        int x = pin[t]; if (t >= off) x += pin[t - off];
        pout[t] = x; __syncthreads();
        int* tmp = pin; pin = pout; pout = tmp;
    }
    if (t < NN) {
        int incl = pin[t];
        g_ptr_o[t + 1] = incl;
        g_cur_o[t] = incl - g_deg_in[t];
        if (t == 0) g_ptr_o[0] = 0;
        g_invdi[t] = (g_deg_in[t] > 0) ? (1.0f / (float)g_deg_in[t]) : 0.0f;
    }
    __syncthreads();
    // --- indptr_i: buckets by row => sizes = deg_out ---
    v = (t < NN) ? g_deg_out[t] : 0;
    sa[t] = v; __syncthreads();
    pin = sa; pout = sb;
    for (int off = 1; off < 1024; off <<= 1) {
        int x = pin[t]; if (t >= off) x += pin[t - off];
        pout[t] = x; __syncthreads();
        int* tmp = pin; pin = pout; pout = tmp;
    }
    if (t < NN) {
        int incl = pin[t];
        g_ptr_i[t + 1] = incl;
        g_cur_i[t] = incl - g_deg_out[t];
        if (t == 0) g_ptr_i[0] = 0;
        g_invdo[t] = (g_deg_out[t] > 0) ? (1.0f / (float)g_deg_out[t]) : 0.0f;
    }
}

__global__ void k_scatter(const int* __restrict__ ei, int E) {
    int e = blockIdx.x * blockDim.x + threadIdx.x;
    if (e < E) {
        int r = ei[e], c = ei[E + e];
        int p = atomicAdd(&g_cur_o[c], 1);
        g_src_o[p] = r;
        g_w_o[p] = g_invdo[r];
        int q = atomicAdd(&g_cur_i[r], 1);
        g_col_i[q] = c;
    }
}

// combined weight: slot 0 = sum over dir of W[.,0]; slots 1..4 = out-dir k; 5..8 = in-dir k
// cols 0..63 from W_z, 64..127 from W_h; only top F input channels (H-half is zero)
__global__ void k_prepw(const float* __restrict__ Wz, const float* __restrict__ Wh,
                        const float* __restrict__ bz, const float* __restrict__ bh) {
    int kidx = blockIdx.x;        // 0..575
    int n = threadIdx.x;          // 0..127
    int slot = kidx >> 6, c = kidx & 63;
    int j = n & 63;
    const float* Wp = (n < 64) ? Wz : Wh;
    float val;
    if (slot == 0) {
        val = Wp[(size_t)(0 * 128 + c) * 64 + j] + Wp[(size_t)(5 * 128 + c) * 64 + j];
    } else if (slot <= 4) {
        val = Wp[(size_t)(slot * 128 + c) * 64 + j];
    } else {
        val = Wp[(size_t)((5 + (slot - 4)) * 128 + c) * 64 + j];
    }
    g_W[kidx * 128 + n] = val;
    if (kidx == 0) g_bias[n] = (n < 64) ? bz[n] : bh[n - 64];
}

__global__ void k_copy(const float* __restrict__ x) {
    int wid = threadIdx.x >> 5, lane = threadIdx.x & 31;
    int row = blockIdx.x * 8 + wid;
    const float2* x2 = (const float2*)x;
    float2 v = x2[(size_t)row * 32 + lane];
    float* d = g_T + (size_t)row * KD + lane * 2;
    d[0] = v.x; d[1] = v.y;
}

// ---------------- diffusion SpMM (Chebyshev step): out = alpha*P(in) - sub ----------------
__global__ void k_spmm(int in_slot, int out_slot, int sub_slot, float alpha, int dir) {
    int wid = threadIdx.x >> 5, lane = threadIdx.x & 31;
    int s = blockIdx.x / 125;
    int nb = blockIdx.x % 125;
    int n = nb * 8 + wid;
    float* base = g_T + (size_t)s * NN * KD;
    float accx = 0.f, accy = 0.f;
    if (dir == 0) {  // prop_out: out[dst] += in[src] / deg_out[src]
        int p0 = g_ptr_o[n], p1 = g_ptr_o[n + 1];
        for (int p = p0; p < p1; ++p) {
            int src = g_src_o[p];
            float w = g_w_o[p];
            const float2 v = *(const float2*)(base + (size_t)src * KD + in_slot * 64 + lane * 2);
            accx = fmaf(w, v.x, accx); accy = fmaf(w, v.y, accy);
        }
    } else {         // prop_in: out[src] = (1/deg_in[src]) * sum in[dst]
        int p0 = g_ptr_i[n], p1 = g_ptr_i[n + 1];
        for (int p = p0; p < p1; ++p) {
            int c = g_col_i[p];
            const float2 v = *(const float2*)(base + (size_t)c * KD + in_slot * 64 + lane * 2);
            accx += v.x; accy += v.y;
        }
        float w = g_invdi[n];
        accx *= w; accy *= w;
    }
    float rx = alpha * accx, ry = alpha * accy;
    if (sub_slot >= 0) {
        const float2 sv = *(const float2*)(base + (size_t)n * KD + sub_slot * 64 + lane * 2);
        rx -= sv.x; ry -= sv.y;
    }
    float* d = base + (size_t)n * KD + out_slot * 64 + lane * 2;
    d[0] = rx; d[1] = ry;
}

// ---------------- tf32 mma.sync GEMM: [192000,576] x [576,128] -> [192000,128] ----------------
__device__ __forceinline__ float to_tf32(float x) {
    uint32_t u; asm("cvt.rna.tf32.f32 %0, %1;" : "=r"(u) : "f"(x));
    return __uint_as_float(u);
}
__device__ __forceinline__ void mma_tf32(float* c, const uint32_t* a, const uint32_t* b) {
    asm volatile("mma.sync.aligned.m16n8k8.row.col.f32.tf32.tf32.f32 "
                 "{%0,%1,%2,%3}, {%4,%5,%6,%7}, {%8,%9}, {%0,%1,%2,%3};\n"
                 : "+f"(c[0]), "+f"(c[1]), "+f"(c[2]), "+f"(c[3])
                 : "r"(a[0]), "r"(a[1]), "r"(a[2]), "r"(a[3]), "r"(b[0]), "r"(b[1]));
}

#define ASTR 36
#define BSTR 136
#define ASZ (128 * ASTR)
#define BSZ (32 * BSTR)

__global__ void __launch_bounds__(256, 1) k_gemm(const float* __restrict__ A,
                                                 const float* __restrict__ B,
                                                 float* __restrict__ C) {
    extern __shared__ float sm[];
    float* As = sm;             // 2 * 128 * 36
    float* Bs = sm + 2 * ASZ;   // 2 * 32 * 136

    const int tid = threadIdx.x;
    const int mbase = blockIdx.x * 128;
    const int ar = tid >> 1, ah = tid & 1;          // A load: row, half (16 floats each)
    const int br = tid >> 3, bc = (tid & 7) * 16;   // B load: k-row, 16-col chunk
    const float* Ag = A + (size_t)mbase * KD;

    float acc[2][8][4];
#pragma unroll
    for (int a = 0; a < 2; ++a)
#pragma unroll
        for (int b = 0; b < 8; ++b)
#pragma unroll
            for (int q = 0; q < 4; ++q) acc[a][b][q] = 0.f;

    float4 la[4], lb[4];
    // prologue: stage 0
    {
        const float4* p = (const float4*)(Ag + (size_t)ar * KD + ah * 16);
#pragma unroll
        for (int j = 0; j < 4; ++j) la[j] = p[j];
        const float4* q = (const float4*)(B + (size_t)br * 128 + bc);
#pragma unroll
        for (int j = 0; j < 4; ++j) lb[j] = q[j];
        float* d = As + ar * ASTR + ah * 16;
#pragma unroll
        for (int j = 0; j < 4; ++j) {
            d[4 * j + 0] = to_tf32(la[j].x); d[4 * j + 1] = to_tf32(la[j].y);
            d[4 * j + 2] = to_tf32(la[j].z); d[4 * j + 3] = to_tf32(la[j].w);
        }
        float* e = Bs + br * BSTR + bc;
#pragma unroll
        for (int j = 0; j < 4; ++j) {
            e[4 * j + 0] = to_tf32(lb[j].x); e[4 * j + 1] = to_tf32(lb[j].y);
            e[4 * j + 2] = to_tf32(lb[j].z); e[4 * j + 3] = to_tf32(lb[j].w);
        }
    }
    __syncthreads();

    const int lane = tid & 31, wid = tid >> 5;
    const int wm = wid & 3, wn = wid >> 2;
    const int g = lane >> 2, tg = lane & 3;

    for (int st = 0; st < NSTAGE; ++st) {
        int buf = st & 1;
        if (st + 1 < NSTAGE) {
            int k0 = (st + 1) * 32;
            const float4* p = (const float4*)(Ag + (size_t)ar * KD + k0 + ah * 16);
#pragma unroll
            for (int j = 0; j < 4; ++j) la[j] = p[j];
            const float4* q = (const float4*)(B + (size_t)(k0 + br) * 128 + bc);
#pragma unroll
            for (int j = 0; j < 4; ++j) lb[j] = q[j];
        }
        const float* Ab = As + buf * ASZ;
        const float* Bb = Bs + buf * BSZ;
#pragma unroll
        for (int kb = 0; kb < 4; ++kb) {
            uint32_t bf[8][2];
#pragma unroll
            for (int nt = 0; nt < 8; ++nt) {
                int n = wn * 64 + nt * 8 + g;
                bf[nt][0] = __float_as_uint(Bb[(kb * 8 + tg) * BSTR + n]);
                bf[nt][1] = __float_as_uint(Bb[(kb * 8 + tg + 4) * BSTR + n]);
            }
#pragma unroll
            for (int mt = 0; mt < 2; ++mt) {
                int R = wm * 32 + mt * 16 + g;
                uint32_t af[4];
                af[0] = __float_as_uint(Ab[R * ASTR + kb * 8 + tg]);
                af[1] = __float_as_uint(Ab[(R + 8) * ASTR + kb * 8 + tg]);
                af[2] = __float_as_uint(Ab[R * ASTR + kb * 8 + tg + 4]);
                af[3] = __float_as_uint(Ab[(R + 8) * ASTR + kb * 8 + tg + 4]);
#pragma unroll
                for (int nt = 0; nt < 8; ++nt) mma_tf32(acc[mt][nt], af, bf[nt]);
            }
        }
        __syncthreads();
        if (st + 1 < NSTAGE) {
            float* d = As + (1 - buf) * ASZ + ar * ASTR + ah * 16;
#pragma unroll
            for (int j = 0; j < 4; ++j) {
                d[4 * j + 0] = to_tf32(la[j].x); d[4 * j + 1] = to_tf32(la[j].y);
                d[4 * j + 2] = to_tf32(la[j].z); d[4 * j + 3] = to_tf32(la[j].w);
            }
            float* e = Bs + (1 - buf) * BSZ + br * BSTR + bc;
#pragma unroll
            for (int j = 0; j < 4; ++j) {
                e[4 * j + 0] = to_tf32(lb[j].x); e[4 * j + 1] = to_tf32(lb[j].y);
                e[4 * j + 2] = to_tf32(lb[j].z); e[4 * j + 3] = to_tf32(lb[j].w);
            }
            __syncthreads();
        }
    }
    // epilogue
#pragma unroll
    for (int mt = 0; mt < 2; ++mt)
#pragma unroll
        for (int nt = 0; nt < 8; ++nt) {
            int Rg = mbase + wm * 32 + mt * 16 + g;
            int Cg = wn * 64 + nt * 8 + 2 * tg;
            float* o = C + (size_t)Rg * 128 + Cg;
            o[0] = acc[mt][nt][0]; o[1] = acc[mt][nt][1];
            float* o2 = C + (size_t)(Rg + 8) * 128 + Cg;
            o2[0] = acc[mt][nt][2]; o2[1] = acc[mt][nt][3];
        }
}

// ---------------- activation + layernorm ----------------
__device__ __forceinline__ float sigf(float x) { return 1.0f / (1.0f + expf(-x)); }

__global__ void k_ln(const float* __restrict__ lng, const float* __restrict__ lnb) {
    int wid = threadIdx.x >> 5, lane = threadIdx.x & 31;
    int row = blockIdx.x * 8 + wid;
    const float* gr = g_gout + (size_t)row * 128;
    float za = gr[lane] + g_bias[lane];
    float zb = gr[lane + 32] + g_bias[lane + 32];
    float ha = gr[64 + lane] + g_bias[64 + lane];
    float hb = gr[96 + lane] + g_bias[96 + lane];
    float va = fmaxf(0.f, (1.f - sigf(za)) * tanhf(ha));
    float vb = fmaxf(0.f, (1.f - sigf(zb)) * tanhf(hb));
    float s = va + vb, sq = va * va + vb * vb;
#pragma unroll
    for (int off = 16; off > 0; off >>= 1) {
        s  += __shfl_xor_sync(0xffffffffu, s, off);
        sq += __shfl_xor_sync(0xffffffffu, sq, off);
    }
    float mean = s * (1.0f / 64.0f);
    float var = sq * (1.0f / 64.0f) - mean * mean;
    float rstd = rsqrtf(var + 1e-5f);
    float* d = g_hn + (size_t)row * 64;
    d[lane]      = (va - mean) * rstd * lng[lane] + lnb[lane];
    d[lane + 32] = (vb - mean) * rstd * lng[lane + 32] + lnb[lane + 32];
}

// ---------------- final linear (two-stage, no float atomics) ----------------
#define CHUNK 16000
__global__ void k_fin1(const float* __restrict__ lw) {
    int bg = blockIdx.x / 48;      // batch group of 4
    int ch = blockIdx.x % 48;
    int tid = threadIdx.x, lane = tid & 31, wid = tid >> 5;
    float a[4][10];
#pragma unroll
    for (int b = 0; b < 4; ++b)
#pragma unroll
        for (int c = 0; c < 10; ++c) a[b][c] = 0.f;
    int i0 = ch * CHUNK, i1 = i0 + CHUNK;
    for (int i = i0 + tid; i < i1; i += 256) {
        float hv[4];
#pragma unroll
        for (int b = 0; b < 4; ++b) hv[b] = g_hn[(size_t)(bg * 4 + b) * 768000 + i];
#pragma unroll
        for (int c = 0; c < 10; ++c) {
            float w = lw[(size_t)c * 768000 + i];
#pragma unroll
            for (int b = 0; b < 4; ++b) a[b][c] = fmaf(hv[b], w, a[b][c]);
        }
    }
    __shared__ float sred[8][40];
    float* av = &a[0][0];
#pragma unroll
    for (int q = 0; q < 40; ++q) {
        float x = av[q];
#pragma unroll
        for (int off = 16; off > 0; off >>= 1) x += __shfl_xor_sync(0xffffffffu, x, off);
        av[q] = x;
    }
    if (lane == 0)
#pragma unroll
        for (int q = 0; q < 40; ++q) sred[wid][q] = av[q];
    __syncthreads();
    if (tid < 40) {
        float ssum = 0.f;
#pragma unroll
        for (int w = 0; w < 8; ++w) ssum += sred[w][tid];
        g_part[blockIdx.x * 40 + tid] = ssum;
    }
}

__global__ void k_fin2(const float* __restrict__ lb, float* __restrict__ out) {
    int t = threadIdx.x;
    if (t < 160) {
        int b = t / 10, c = t % 10;
        int bg = b >> 2, bb = b & 3;
        float s = lb[c];
        for (int ch = 0; ch < 48; ++ch) s += g_part[(bg * 48 + ch) * 40 + bb * 10 + c];
        out[t] = s;
    }
}

// ---------------- launch ----------------
extern "C" void kernel_launch(void* const* d_in, const int* in_sizes, int n_in,
                              void* d_out, int out_size) {
    const float* x   = (const float*)d_in[0];
    const int*   ei  = (const int*)d_in[1];
    const float* Wz  = (const float*)d_in[2];
    const float* bz  = (const float*)d_in[3];
    const float* Wh  = (const float*)d_in[6];
    const float* bh  = (const float*)d_in[7];
    const float* lng = (const float*)d_in[8];
    const float* lnb = (const float*)d_in[9];
    const float* lw  = (const float*)d_in[10];
    const float* lb  = (const float*)d_in[11];
    int E = in_sizes[1] / 2;

    const int smem_gemm = (2 * ASZ + 2 * BSZ) * 4;
    cudaFuncSetAttribute(k_gemm, cudaFuncAttributeMaxDynamicSharedMemorySize, smem_gemm);

    float* dT;  cudaGetSymbolAddress((void**)&dT, g_T);
    float* dGo; cudaGetSymbolAddress((void**)&dGo, g_gout);
    float* dW;  cudaGetSymbolAddress((void**)&dW, g_W);

    k_zero<<<1, 256>>>();
    k_deg<<<(E + 255) / 256, 256>>>(ei, E);
    k_scan<<<1, 1024>>>();
    k_scatter<<<(E + 255) / 256, 256>>>(ei, E);
    k_prepw<<<KD, 128>>>(Wz, Wh, bz, bh);
    k_copy<<<24000, 256>>>(x);

    // Chebyshev chain (note the reference's Tx0 <- Tx1o shift: I-direction subtracts O history)
    k_spmm<<<24000, 256>>>(0, 1, -1, 1.f, 0);  // O1 = P_o(x)
    k_spmm<<<24000, 256>>>(0, 5, -1, 1.f, 1);  // I1 = P_i(x)
    k_spmm<<<24000, 256>>>(1, 2, 0, 2.f, 0);   // O2 = 2 P_o(O1) - x
    k_spmm<<<24000, 256>>>(5, 6, 0, 2.f, 1);   // I2 = 2 P_i(I1) - x
    k_spmm<<<24000, 256>>>(2, 3, 1, 2.f, 0);   // O3 = 2 P_o(O2) - O1
    k_spmm<<<24000, 256>>>(6, 7, 1, 2.f, 1);   // I3 = 2 P_i(I2) - O1
    k_spmm<<<24000, 256>>>(3, 4, 2, 2.f, 0);   // O4 = 2 P_o(O3) - O2
    k_spmm<<<24000, 256>>>(7, 8, 2, 2.f, 1);   // I4 = 2 P_i(I3) - O2

    k_gemm<<<1500, 256, smem_gemm>>>(dT, dW, dGo);
    k_ln<<<24000, 256>>>(lng, lnb);
    k_fin1<<<192, 256>>>(lw);
    k_fin2<<<1, 192>>>(lb, (float*)d_out);
}